// round 1
// baseline (speedup 1.0000x reference)
#include <cuda_runtime.h>
#include <cuda_bf16.h>

// Problem constants (shapes fixed by the dataset):
//   preds: [128, 4096, 50] float32 -> 26,214,400 elements (d_in[0])
//   gt:    [128, 4096]     int32   ->    524,288 elements (d_in[1])
//   out:   scalar float32
//
// loss = sum_{voiced rows} [ sum_n softplus(p_n) - sum_n p_n * tgt_n ] / (50 * n_voiced)
// tgt is a 5-tap gaussian blur (reflect pad) of one_hot(q); support <= 5 bins.

#define N_ELEMS   26214400u
#define NF4       6553600u      // N_ELEMS / 4
#define ROWS      524288
#define NBINS     50

#define SP_BLOCKS  1216         // 152 SMs * 8
#define SP_THREADS 256
#define RD_THREADS 256
#define RD_BLOCKS  (ROWS / RD_THREADS)   // 2048

// Per-block partials (fully overwritten every launch -> graph-replay safe,
// no init kernel, no atomics, deterministic reduction order).
__device__ float g_sp [SP_BLOCKS];   // sum of log2(1 + exp(p)) over voiced elems
__device__ float g_dot[RD_BLOCKS];   // sum of p . tgt over voiced rows
__device__ int   g_cnt[RD_BLOCKS];   // voiced row count

// Gaussian kernel (sigma=0.5, ks=5): exp(-2x^2)/sum, x=-2..2
__device__ __forceinline__ float gk(int i) {
    const float K0 = 2.6386456e-4f;
    const float K1 = 0.10645078f;
    const float K2 = 0.78657072f;
    return (i == 2) ? K2 : ((i == 1 || i == 3) ? K1 : K0);
}

__device__ __forceinline__ int quant_q(int g) {
    // q = clip(floor((g-50)/6), 0, 49); g integer so int division matches for g>=50
    return (g > 50) ? min((g - 50) / 6, NBINS - 1) : 0;
}

// ---------------------------------------------------------------------------
// Kernel 1: streaming softplus sum over all elements, weighted by voiced flag.
// ---------------------------------------------------------------------------
__global__ __launch_bounds__(SP_THREADS) void softplus_kernel(
    const float* __restrict__ preds, const int* __restrict__ gt)
{
    float acc = 0.0f;
    const unsigned stride = gridDim.x * blockDim.x;
    for (unsigned i = blockIdx.x * blockDim.x + threadIdx.x; i < NF4; i += stride) {
        float4 v = reinterpret_cast<const float4*>(preds)[i];
        unsigned e0 = i * 4u;
        unsigned r0 = e0 / 50u;
        unsigned r3 = (e0 + 3u) / 50u;
        int g0 = __ldg(gt + r0);
        int g3 = __ldg(gt + r3);
        float w0 = (g0 != 100) ? 1.0f : 0.0f;
        float w3 = (g3 != 100) ? 1.0f : 0.0f;
        unsigned b = r3 * 50u;   // first element index belonging to row r3
        // element k belongs to row r3 iff e0+k >= b (if r0==r3, b<=e0 so all w3==w0)
        float wa = (e0 + 0u < b) ? w0 : w3;
        float wb = (e0 + 1u < b) ? w0 : w3;
        float wc = (e0 + 2u < b) ? w0 : w3;
        float wd = (e0 + 3u < b) ? w0 : w3;

        // log2(1 + exp(p)) : FMUL+EX2, FADD, LG2, FFMA  (2 MUFU / elem)
        float la = __log2f(1.0f + __expf(v.x));
        float lb = __log2f(1.0f + __expf(v.y));
        float lc = __log2f(1.0f + __expf(v.z));
        float ld = __log2f(1.0f + __expf(v.w));
        acc = fmaf(wa, la, acc);
        acc = fmaf(wb, lb, acc);
        acc = fmaf(wc, lc, acc);
        acc = fmaf(wd, ld, acc);
    }

    __shared__ float s[SP_THREADS];
    int tid = threadIdx.x;
    s[tid] = acc;
    __syncthreads();
    #pragma unroll
    for (int o = SP_THREADS / 2; o > 0; o >>= 1) {
        if (tid < o) s[tid] += s[tid + o];
        __syncthreads();
    }
    if (tid == 0) g_sp[blockIdx.x] = s[0];
}

// ---------------------------------------------------------------------------
// Kernel 2: per-row dot(p, tgt) over the <=5-bin blur support + voiced count.
// ---------------------------------------------------------------------------
__global__ __launch_bounds__(RD_THREADS) void rowdot_kernel(
    const float* __restrict__ preds, const int* __restrict__ gt)
{
    int r = blockIdx.x * RD_THREADS + threadIdx.x;
    int g = gt[r];
    int voiced = (g != 100) ? 1 : 0;
    float dot = 0.0f;
    if (voiced) {
        int q = quant_q(g);
        const float* row = preds + (size_t)r * NBINS;
        #pragma unroll
        for (int j = -2; j <= 2; j++) {
            int n = q + j;
            if (n < 0 || n > NBINS - 1) continue;
            // tgt[n] = sum_i k[i] * [reflect(n+i-2) == q]
            float t = 0.0f;
            #pragma unroll
            for (int i = 0; i < 5; i++) {
                int m = n + i - 2;
                int mm = (m < 0) ? -m : ((m > NBINS - 1) ? (2 * (NBINS - 1) - m) : m);
                if (mm == q) t += gk(i);
            }
            dot = fmaf(__ldg(row + n), t, dot);
        }
    }

    __shared__ float sd[RD_THREADS];
    __shared__ int   sc[RD_THREADS];
    int tid = threadIdx.x;
    sd[tid] = dot;
    sc[tid] = voiced;
    __syncthreads();
    #pragma unroll
    for (int o = RD_THREADS / 2; o > 0; o >>= 1) {
        if (tid < o) { sd[tid] += sd[tid + o]; sc[tid] += sc[tid + o]; }
        __syncthreads();
    }
    if (tid == 0) { g_dot[blockIdx.x] = sd[0]; g_cnt[blockIdx.x] = sc[0]; }
}

// ---------------------------------------------------------------------------
// Kernel 3: final deterministic reduction + scalar write.
// ---------------------------------------------------------------------------
__global__ __launch_bounds__(256) void finalize_kernel(float* __restrict__ out)
{
    __shared__ float ssp[256];
    __shared__ float sdt[256];
    __shared__ int   sct[256];
    int tid = threadIdx.x;

    float a = 0.0f;
    for (int i = tid; i < SP_BLOCKS; i += 256) a += g_sp[i];
    float d = 0.0f; int c = 0;
    for (int i = tid; i < RD_BLOCKS; i += 256) { d += g_dot[i]; c += g_cnt[i]; }

    ssp[tid] = a; sdt[tid] = d; sct[tid] = c;
    __syncthreads();
    #pragma unroll
    for (int o = 128; o > 0; o >>= 1) {
        if (tid < o) {
            ssp[tid] += ssp[tid + o];
            sdt[tid] += sdt[tid + o];
            sct[tid] += sct[tid + o];
        }
        __syncthreads();
    }
    if (tid == 0) {
        const float LN2 = 0.69314718055994530942f;
        float total = LN2 * ssp[0] - sdt[0];
        out[0] = total / (50.0f * (float)sct[0]);
    }
}

extern "C" void kernel_launch(void* const* d_in, const int* in_sizes, int n_in,
                              void* d_out, int out_size)
{
    const float* preds = (const float*)d_in[0];
    const int*   gt    = (const int*)d_in[1];
    float* out = (float*)d_out;

    softplus_kernel<<<SP_BLOCKS, SP_THREADS>>>(preds, gt);
    rowdot_kernel<<<RD_BLOCKS, RD_THREADS>>>(preds, gt);
    finalize_kernel<<<1, 256>>>(out);
}

// round 2
// speedup vs baseline: 1.0987x; 1.0987x over previous
#include <cuda_runtime.h>
#include <cuda_bf16.h>

// preds: [128, 4096, 50] float32 -> 26,214,400 elems (d_in[0])
// gt:    [128, 4096]     int32   ->    524,288 elems (d_in[1])
// out:   scalar float32
//
// loss = [ LN2*(sum_all log2(1+exp(p)) - sum_{unvoiced rows} log2(1+exp(p)))
//          - sum_{voiced rows} p.tgt ] / (50 * n_voiced)
// tgt is a 5-tap gaussian blur (reflect) of one_hot(q); support <= 5 bins.
// Unvoiced rows (gt==100) are ~0.5% -> handled in the cheap per-row kernel.

#define N_ELEMS   26214400u
#define NF4       6553600u      // N_ELEMS / 4
#define ROWS      524288
#define NBINS     50

#define SP_BLOCKS  1216         // 152 SMs * 8
#define SP_THREADS 256
#define RD_THREADS 256
#define RD_BLOCKS  (ROWS / RD_THREADS)   // 2048

// Per-block partials (fully overwritten every launch -> graph-replay safe).
__device__ float g_sp  [SP_BLOCKS];   // sum over ALL elems of log2(1+exp(p))
__device__ float g_dot [RD_BLOCKS];   // sum of p.tgt over voiced rows
__device__ float g_neg [RD_BLOCKS];   // sum over UNVOICED rows of log2(1+exp(p))
__device__ int   g_cnt [RD_BLOCKS];   // voiced row count

// Gaussian kernel (sigma=0.5, ks=5)
__device__ __forceinline__ float gk(int i) {
    const float K0 = 2.6386456e-4f;
    const float K1 = 0.10645078f;
    const float K2 = 0.78657072f;
    return (i == 2) ? K2 : ((i == 1 || i == 3) ? K1 : K0);
}

__device__ __forceinline__ int quant_q(int g) {
    return (g > 50) ? min((g - 50) / 6, NBINS - 1) : 0;
}

__device__ __forceinline__ float sp2(float p) {       // log2(1 + exp(p))
    return __log2f(1.0f + __expf(p));
}

// ---------------------------------------------------------------------------
// Kernel 1: pure streaming softplus sum over ALL elements. No gt, no masks.
// ---------------------------------------------------------------------------
__global__ __launch_bounds__(SP_THREADS) void softplus_kernel(
    const float* __restrict__ preds)
{
    const unsigned stride = gridDim.x * blockDim.x;
    const float4* p4 = reinterpret_cast<const float4*>(preds);

    float acc0 = 0.0f, acc1 = 0.0f, acc2 = 0.0f, acc3 = 0.0f;
    unsigned i = blockIdx.x * blockDim.x + threadIdx.x;

    // 4x unrolled grid-stride: 4 independent LDG.128 in flight.
    for (; i + 3u * stride < NF4; i += 4u * stride) {
        float4 a = p4[i];
        float4 b = p4[i + stride];
        float4 c = p4[i + 2u * stride];
        float4 d = p4[i + 3u * stride];
        acc0 += sp2(a.x) + sp2(a.y) + sp2(a.z) + sp2(a.w);
        acc1 += sp2(b.x) + sp2(b.y) + sp2(b.z) + sp2(b.w);
        acc2 += sp2(c.x) + sp2(c.y) + sp2(c.z) + sp2(c.w);
        acc3 += sp2(d.x) + sp2(d.y) + sp2(d.z) + sp2(d.w);
    }
    for (; i < NF4; i += stride) {
        float4 a = p4[i];
        acc0 += sp2(a.x) + sp2(a.y) + sp2(a.z) + sp2(a.w);
    }
    float acc = (acc0 + acc1) + (acc2 + acc3);

    __shared__ float s[SP_THREADS];
    int tid = threadIdx.x;
    s[tid] = acc;
    __syncthreads();
    #pragma unroll
    for (int o = SP_THREADS / 2; o > 0; o >>= 1) {
        if (tid < o) s[tid] += s[tid + o];
        __syncthreads();
    }
    if (tid == 0) g_sp[blockIdx.x] = s[0];
}

// ---------------------------------------------------------------------------
// Kernel 2: per-row work. Voiced: dot(p, tgt) over <=5-bin support.
//           Unvoiced (~0.5%): subtract that row's 50-elem softplus (log2 dom).
// ---------------------------------------------------------------------------
__global__ __launch_bounds__(RD_THREADS) void rowdot_kernel(
    const float* __restrict__ preds, const int* __restrict__ gt)
{
    int r = blockIdx.x * RD_THREADS + threadIdx.x;
    int g = gt[r];
    int voiced = (g != 100) ? 1 : 0;
    const float* row = preds + (size_t)r * NBINS;

    float dot = 0.0f;
    float neg = 0.0f;
    if (voiced) {
        int q = quant_q(g);
        #pragma unroll
        for (int j = -2; j <= 2; j++) {
            int n = q + j;
            if (n < 0 || n > NBINS - 1) continue;
            float t = 0.0f;
            #pragma unroll
            for (int i = 0; i < 5; i++) {
                int m = n + i - 2;
                int mm = (m < 0) ? -m : ((m > NBINS - 1) ? (2 * (NBINS - 1) - m) : m);
                if (mm == q) t += gk(i);
            }
            dot = fmaf(__ldg(row + n), t, dot);
        }
    } else {
        #pragma unroll 5
        for (int n = 0; n < NBINS; n++)
            neg += sp2(__ldg(row + n));
    }

    __shared__ float sd[RD_THREADS];
    __shared__ float sn[RD_THREADS];
    __shared__ int   sc[RD_THREADS];
    int tid = threadIdx.x;
    sd[tid] = dot; sn[tid] = neg; sc[tid] = voiced;
    __syncthreads();
    #pragma unroll
    for (int o = RD_THREADS / 2; o > 0; o >>= 1) {
        if (tid < o) {
            sd[tid] += sd[tid + o];
            sn[tid] += sn[tid + o];
            sc[tid] += sc[tid + o];
        }
        __syncthreads();
    }
    if (tid == 0) { g_dot[blockIdx.x] = sd[0]; g_neg[blockIdx.x] = sn[0]; g_cnt[blockIdx.x] = sc[0]; }
}

// ---------------------------------------------------------------------------
// Kernel 3: final deterministic reduction + scalar write.
// ---------------------------------------------------------------------------
__global__ __launch_bounds__(256) void finalize_kernel(float* __restrict__ out)
{
    __shared__ float ssp[256];
    __shared__ float sdt[256];
    __shared__ float sng[256];
    __shared__ int   sct[256];
    int tid = threadIdx.x;

    float a = 0.0f;
    for (int i = tid; i < SP_BLOCKS; i += 256) a += g_sp[i];
    float d = 0.0f, n = 0.0f; int c = 0;
    for (int i = tid; i < RD_BLOCKS; i += 256) {
        d += g_dot[i]; n += g_neg[i]; c += g_cnt[i];
    }

    ssp[tid] = a; sdt[tid] = d; sng[tid] = n; sct[tid] = c;
    __syncthreads();
    #pragma unroll
    for (int o = 128; o > 0; o >>= 1) {
        if (tid < o) {
            ssp[tid] += ssp[tid + o];
            sdt[tid] += sdt[tid + o];
            sng[tid] += sng[tid + o];
            sct[tid] += sct[tid + o];
        }
        __syncthreads();
    }
    if (tid == 0) {
        const float LN2 = 0.69314718055994530942f;
        float total = LN2 * (ssp[0] - sng[0]) - sdt[0];
        out[0] = total / (50.0f * (float)sct[0]);
    }
}

extern "C" void kernel_launch(void* const* d_in, const int* in_sizes, int n_in,
                              void* d_out, int out_size)
{
    const float* preds = (const float*)d_in[0];
    const int*   gt    = (const int*)d_in[1];
    float* out = (float*)d_out;

    softplus_kernel<<<SP_BLOCKS, SP_THREADS>>>(preds);
    rowdot_kernel<<<RD_BLOCKS, RD_THREADS>>>(preds, gt);
    finalize_kernel<<<1, 256>>>(out);
}

// round 3
// speedup vs baseline: 1.3364x; 1.2164x over previous
#include <cuda_runtime.h>
#include <cuda_bf16.h>

// preds: [128, 4096, 50] float32 -> 26,214,400 elems (d_in[0])
// gt:    [128, 4096]     int32   ->    524,288 elems (d_in[1])
// out:   scalar float32
//
// loss = [ LN2*(sum_all log2(1+exp(p)) - sum_{unvoiced} log2(1+exp(p)))
//          - sum_{voiced} p.tgt ] / (50 * n_voiced)
// tgt = 5-tap gaussian blur (reflect) of one_hot(q); support <= 5 bins.
// Single fused kernel; last block finalizes (deterministic ordered reduce).

#define N_ELEMS   26214400u
#define NF4       6553600u
#define ROWS      524288u
#define NBINS     50

#define SP_BLOCKS  1216
#define SP_THREADS 256
#define NTHREADS   (SP_BLOCKS * SP_THREADS)   // 311296

__device__ float    g_part[SP_BLOCKS];  // per-block: LN2*(sp-neg) - dot
__device__ int      g_cntp[SP_BLOCKS];  // per-block voiced count
__device__ unsigned g_done;             // ticket; reset to 0 by last block

__device__ __forceinline__ float gk(int i) {
    const float K0 = 2.6386456e-4f;
    const float K1 = 0.10645078f;
    const float K2 = 0.78657072f;
    return (i == 2) ? K2 : ((i == 1 || i == 3) ? K1 : K0);
}

__device__ __forceinline__ int quant_q(int g) {
    return (g > 50) ? min((g - 50) / 6, NBINS - 1) : 0;
}

__device__ __forceinline__ float sp2(float p) {   // log2(1 + exp(p))
    return __log2f(1.0f + __expf(p));
}

// prod *= (1 + exp(p))  ==  fma(prod, exp(p), prod)
__device__ __forceinline__ void pmul(float& pr, float p) {
    pr = fmaf(pr, __expf(p), pr);
}

__global__ __launch_bounds__(SP_THREADS) void pitchloss_kernel(
    const float* __restrict__ preds, const int* __restrict__ gt,
    float* __restrict__ out)
{
    const int      tid  = threadIdx.x;
    const unsigned gtid = blockIdx.x * SP_THREADS + tid;

    // ---------------- per-row work (voiced dot / unvoiced correction) -----
    float dot = 0.0f, neg = 0.0f;
    int   cnt = 0;
    for (unsigned r = gtid; r < ROWS; r += NTHREADS) {
        int g = gt[r];
        const float* row = preds + (size_t)r * NBINS;
        if (g != 100) {
            cnt++;
            int q = quant_q(g);
            #pragma unroll
            for (int j = -2; j <= 2; j++) {
                int n = q + j;
                if (n < 0 || n > NBINS - 1) continue;
                float t = 0.0f;
                #pragma unroll
                for (int i = 0; i < 5; i++) {
                    int m = n + i - 2;
                    int mm = (m < 0) ? -m : ((m > NBINS - 1) ? (2*(NBINS-1) - m) : m);
                    if (mm == q) t += gk(i);
                }
                dot = fmaf(__ldg(row + n), t, dot);
            }
        } else {
            #pragma unroll 5
            for (int n = 0; n < NBINS; n++)
                neg += sp2(__ldg(row + n));
        }
    }

    // ---------------- streaming softplus over ALL elements ----------------
    // log2 of 8-term product: 8x EX2 + 1x LG2 per 8 elements.
    const float4* p4 = reinterpret_cast<const float4*>(preds);
    float acc = 0.0f;
    unsigned i = gtid;
    for (; i + 3u * NTHREADS < NF4; i += 4u * NTHREADS) {
        float4 a = p4[i];
        float4 b = p4[i +      NTHREADS];
        float4 c = p4[i + 2u * NTHREADS];
        float4 d = p4[i + 3u * NTHREADS];
        float pr1 = 1.0f + __expf(a.x);
        pmul(pr1, a.y); pmul(pr1, a.z); pmul(pr1, a.w);
        pmul(pr1, b.x); pmul(pr1, b.y); pmul(pr1, b.z); pmul(pr1, b.w);
        float pr2 = 1.0f + __expf(c.x);
        pmul(pr2, c.y); pmul(pr2, c.z); pmul(pr2, c.w);
        pmul(pr2, d.x); pmul(pr2, d.y); pmul(pr2, d.z); pmul(pr2, d.w);
        acc += __log2f(pr1) + __log2f(pr2);
    }
    for (; i < NF4; i += NTHREADS) {
        float4 a = p4[i];
        float pr = 1.0f + __expf(a.x);
        pmul(pr, a.y); pmul(pr, a.z); pmul(pr, a.w);
        acc += __log2f(pr);
    }

    // ---------------- block reduction -------------------------------------
    const float LN2 = 0.69314718055994530942f;
    float part = fmaf(LN2, acc - neg, -dot);

    __shared__ float sp[SP_THREADS];
    __shared__ int   sc[SP_THREADS];
    sp[tid] = part; sc[tid] = cnt;
    __syncthreads();
    #pragma unroll
    for (int o = SP_THREADS / 2; o > 0; o >>= 1) {
        if (tid < o) { sp[tid] += sp[tid + o]; sc[tid] += sc[tid + o]; }
        __syncthreads();
    }

    __shared__ bool s_last;
    if (tid == 0) {
        g_part[blockIdx.x] = sp[0];
        g_cntp[blockIdx.x] = sc[0];
        __threadfence();
        unsigned t = atomicAdd(&g_done, 1u);
        s_last = (t == SP_BLOCKS - 1);
    }
    __syncthreads();

    // ---------------- last block: deterministic ordered finalize ----------
    if (s_last) {
        float a = 0.0f; int c = 0;
        for (int j = tid; j < SP_BLOCKS; j += SP_THREADS) {
            a += g_part[j]; c += g_cntp[j];
        }
        sp[tid] = a; sc[tid] = c;
        __syncthreads();
        #pragma unroll
        for (int o = SP_THREADS / 2; o > 0; o >>= 1) {
            if (tid < o) { sp[tid] += sp[tid + o]; sc[tid] += sc[tid + o]; }
            __syncthreads();
        }
        if (tid == 0) {
            out[0] = sp[0] / (50.0f * (float)sc[0]);
            g_done = 0;   // reset for next (graph-replayed) launch
        }
    }
}

extern "C" void kernel_launch(void* const* d_in, const int* in_sizes, int n_in,
                              void* d_out, int out_size)
{
    const float* preds = (const float*)d_in[0];
    const int*   gt    = (const int*)d_in[1];
    float* out = (float*)d_out;

    pitchloss_kernel<<<SP_BLOCKS, SP_THREADS>>>(preds, gt, out);
}